// round 13
// baseline (speedup 1.0000x reference)
#include <cuda_runtime.h>
#include <cuda_bf16.h>
#include <math.h>

// Problem constants: B=4, MAX_T=200, MAX_U=101, VOCAB=1024
#define BB 4
#define TT 200
#define UU 101
#define UP 104                    // padded U stride (16B alignment for float4)
#define VV 1024
#define DD (TT + UU - 1)          // 300 anti-diagonals
#define NCELLS (BB * TT * UU)     // 80800
#define PFD 6                     // alpha prefetch depth (diagonals)

// Scratch. Diagonal-major, padded, interleaved: g_probD[b][d*UP+u] = {blank_lp, label_lp}
__device__ __align__(16) float2 g_probD[BB * DD * UP];
__device__ int g_cnt[BB][DD];     // completed live cells per (b, diag); zero-init, alpha resets
__device__ float g_loss[BB];
__device__ int   g_valid[BB];
__device__ unsigned g_ticket;     // zero-init; last alpha block resets after use

// ---------------------------------------------------------------------------
// Per-warp helpers (all 32 lanes participate). int64 labels < 1024 => every
// odd int32 word is 0 (P[false positive] ~ 1024^-64).
// ---------------------------------------------------------------------------
__device__ __forceinline__ int warp_detect_is64(const int* __restrict__ labels_i32)
{
    const int lane = threadIdx.x & 31;
    int ok = 1;
#pragma unroll
    for (int i = 1 + 2 * lane; i < 256; i += 64)
        ok &= (labels_i32[i] == 0);
    return __all_sync(0xffffffffu, ok);
}

__device__ __forceinline__ int warp_input_len(const int* __restrict__ attention_mask, int b)
{
    const int lane = threadIdx.x & 31;
    int acc = 0;
#pragma unroll
    for (int k = lane; k < TT; k += 32)
        acc += attention_mask[b * TT + k];
#pragma unroll
    for (int off = 16; off > 0; off >>= 1)
        acc += __shfl_xor_sync(0xffffffffu, acc, off);
    return acc < 1 ? 1 : (acc > TT ? TT : acc);
}

__device__ __forceinline__ int load_int(const void* p, int idx, int is64)
{
    return is64 ? (int)((const long long*)p)[idx] : ((const int*)p)[idx];
}

// Number of LIVE cells on diagonal d for sample with lengths (il, ll).
__device__ __forceinline__ int live_count(int d, int il, int ll)
{
    int lo = d - (il - 1); lo = lo > 0 ? lo : 0;
    int hi = d < ll ? d : ll;
    int n = hi - lo + 1;
    return n > 0 ? n : 0;
}

// Wait (warp-parallel poll) until diagonals [lo, hi] of sample b are complete.
__device__ __forceinline__ void wait_diags(int b, int lo, int hi, int il, int ll)
{
    if (lo > hi) return;                         // warp-uniform
    const int lane = threadIdx.x & 31;
    const int k = lo + lane;
    const bool mine = (k <= hi);
    const int need = mine ? live_count(k, il, ll) : 0;
    const volatile int* c = &g_cnt[b][mine ? k : hi];
    while (true) {
        const int have = mine ? *c : 0;
        if (__all_sync(0xffffffffu, have >= need)) break;
        __nanosleep(128);
    }
    __threadfence();                             // acquire probD writes
}

// ---------------------------------------------------------------------------
// alpha consumer: one warp, 4 u-values per lane, branch-free inner loop
// (R12 design), pipelined against the lse producers via g_cnt.
// ---------------------------------------------------------------------------
__device__ __forceinline__ float stepcell(float top, float left,
                                          float blank, float label,
                                          int t, int u)
{
    const float viaB = top + blank;
    const float viaL = left + label;
    const float mx = fmaxf(viaB, viaL);
    const float mn = fminf(viaB, viaL);
    const float both = mx + __logf(1.f + __expf(mn - mx));
    float r = (t == 0) ? viaL : both;              // label-only top row
    r = (u == 0) ? ((t == 0) ? blank : viaB) : r;  // blank-only column / origin
    return r;
}

__device__ __forceinline__ void alpha_warp(int b,
                                           const void* __restrict__ labels,
                                           const void* __restrict__ label_lengths,
                                           const int* __restrict__ attention_mask,
                                           float* __restrict__ out)
{
    const int lane = threadIdx.x & 31;

    const int is64 = warp_detect_is64((const int*)labels);
    const int il = warp_input_len(attention_mask, b);
    int ll = load_int(label_lengths, b, is64);
    ll = ll < 0 ? 0 : (ll > UU - 1 ? UU - 1 : ll);
    const int target_d = (il - 1) + ll;

    const float2* pD = g_probD + b * (DD * UP);
    const int u0 = lane * 4;
    const int uL = (u0 <= 100) ? u0 : 100;   // EVEN -> float4-aligned, <= UP-4

    // Wait for + prefetch diagonals 0..PFD-1 (only those that get consumed).
    wait_diags(b, 0, (PFD - 1) < target_d ? (PFD - 1) : target_d, il, ll);

    float4 pA0, pB0, pA1, pB1, pA2, pB2, pA3, pB3, pA4, pB4, pA5, pB5;
#define PF_LOAD(PA, PB, K)                                                    \
    {                                                                         \
        const float4* p_ = (const float4*)(pD + (K) * UP + uL);               \
        PA = p_[0]; PB = p_[1];                                               \
    }
    PF_LOAD(pA0, pB0, 0) PF_LOAD(pA1, pB1, 1) PF_LOAD(pA2, pB2, 2)
    PF_LOAD(pA3, pB3, 3) PF_LOAD(pA4, pB4, 4) PF_LOAD(pA5, pB5, 5)
#undef PF_LOAD

    float a0 = 0.f, a1 = 0.f, a2 = 0.f, a3 = 0.f;   // alpha(d-1, u0..u0+3)

#define ALPHA_STEP(PA, PB, DCUR)                                              \
    {                                                                         \
        const float4 cA = PA, cB = PB;                                        \
        const int dn = (DCUR) + PFD;                                          \
        const int dnc = dn < DD ? dn : DD - 1;                                \
        const float4* pp = (const float4*)(pD + dnc * UP + uL);               \
        PA = pp[0]; PB = pp[1];                                               \
        const float left0 = __shfl_up_sync(0xffffffffu, a3, 1);               \
        const int t0 = (DCUR) - u0;                                           \
        const float n0 = stepcell(a0, left0, cA.x, cA.y, t0,     u0);         \
        const float n1 = stepcell(a1, a0,    cA.z, cA.w, t0 - 1, u0 + 1);     \
        const float n2 = stepcell(a2, a1,    cB.x, cB.y, t0 - 2, u0 + 2);     \
        const float n3 = stepcell(a3, a2,    cB.z, cB.w, t0 - 3, u0 + 3);     \
        a0 = n0; a1 = n1; a2 = n2; a3 = n3;                                   \
    }

    int d = 0;
    for (; d + (PFD - 1) <= target_d; d += PFD) {
        // Ensure the diagonals this block will PREFETCH (and later consume)
        // are fully produced. Everything below d+PFD was waited earlier.
        {
            const int whi = (d + 2 * PFD - 1) < target_d ? (d + 2 * PFD - 1) : target_d;
            wait_diags(b, d + PFD, whi, il, ll);
        }
        ALPHA_STEP(pA0, pB0, d)
        ALPHA_STEP(pA1, pB1, d + 1)
        ALPHA_STEP(pA2, pB2, d + 2)
        ALPHA_STEP(pA3, pB3, d + 3)
        ALPHA_STEP(pA4, pB4, d + 4)
        ALPHA_STEP(pA5, pB5, d + 5)
    }
    // tail: warp-uniform guards; data already waited+prefetched
    if (d     <= target_d) ALPHA_STEP(pA0, pB0, d)
    if (d + 1 <= target_d) ALPHA_STEP(pA1, pB1, d + 1)
    if (d + 2 <= target_d) ALPHA_STEP(pA2, pB2, d + 2)
    if (d + 3 <= target_d) ALPHA_STEP(pA3, pB3, d + 3)
    if (d + 4 <= target_d) ALPHA_STEP(pA4, pB4, d + 4)
#undef ALPHA_STEP

    // Result: alpha(target_d, ll) lives in lane ll>>2, slot ll&3.
    const int src_lane = ll >> 2;
    const int sub = ll & 3;
    const float r0 = __shfl_sync(0xffffffffu, a0, src_lane);
    const float r1 = __shfl_sync(0xffffffffu, a1, src_lane);
    const float r2 = __shfl_sync(0xffffffffu, a2, src_lane);
    const float r3 = __shfl_sync(0xffffffffu, a3, src_lane);
    const float r = (sub == 0) ? r0 : (sub == 1) ? r1 : (sub == 2) ? r2 : r3;

    // Reset this sample's counters for the next graph replay. Safe: all live
    // cells have t+u <= target_d and alpha observed every such counter full,
    // so no increment for sample b can still be in flight.
    for (int k = lane; k < DD; k += 32) g_cnt[b][k] = 0;

    if (lane == 0) {
        const bool valid = (il > 0) && (ll > 0);
        g_loss[b] = valid ? -r : 0.f;
        g_valid[b] = valid ? 1 : 0;

        __threadfence();
        const unsigned tk = atomicAdd(&g_ticket, 1u);
        if (tk == BB - 1) {
            __threadfence();
            float s = 0.f;
            int nv = 0;
#pragma unroll
            for (int i = 0; i < BB; i++) { s += g_loss[i]; nv += g_valid[i]; }
            out[0] = s / (float)(nv > 0 ? nv : 1);
            g_ticket = 0;
            __threadfence();
        }
    }
}

// ---------------------------------------------------------------------------
// Fused kernel. Blocks 0..BB-1: alpha consumers (warp 0 only), resident from
// wave 1. Remaining blocks: lse producers, one warp per live cell, sample-
// interleaved (b = gid & 3) so all 4 samples are produced in t-order in
// lockstep. Producers never wait -> deadlock-free regardless of scheduling.
// ---------------------------------------------------------------------------
__global__ void __launch_bounds__(256)
fused_kernel(const float* __restrict__ logits,
             const void* __restrict__ labels,
             const void* __restrict__ label_lengths,
             const int* __restrict__ attention_mask,
             float* __restrict__ out)
{
    if (blockIdx.x < BB) {
        if (threadIdx.x < 32)
            alpha_warp(blockIdx.x, labels, label_lengths, attention_mask, out);
        return;
    }

    const int warp = threadIdx.x >> 5;
    const int lane = threadIdx.x & 31;
    const int gid = (blockIdx.x - BB) * 8 + warp;
    if (gid >= NCELLS) return;

    const int b = gid & 3;                 // sample-interleaved production
    const int rem = gid >> 2;              // (t,u) linear index, t-major
    const int t = rem / UU;
    const int u = rem - t * UU;

    const int is64 = warp_detect_is64((const int*)labels);
    int ll = load_int(label_lengths, b, is64);
    ll = ll < 0 ? 0 : (ll > UU - 1 ? UU - 1 : ll);
    const int il = warp_input_len(attention_mask, b);
    if (u > ll || t >= il) return;         // dead cell: no loads, no counter

    const float* base = logits + ((size_t)b * (TT * UU) + rem) * VV;
    const float4* p = (const float4*)base;

    float s = 0.f;
    float first = 0.f;   // lane 0, i=0, .x == blank logit
#pragma unroll
    for (int i = 0; i < 8; i++) {
        float4 v = __ldcs(p + i * 32 + lane);      // streaming: keep probD in L2
        if (i == 0) first = v.x;
        s += __expf(v.x) + __expf(v.y) + __expf(v.z) + __expf(v.w);
    }
#pragma unroll
    for (int off = 16; off > 0; off >>= 1)
        s += __shfl_xor_sync(0xffffffffu, s, off);

    const float lse = __logf(s);

    if (lane == 0) {
        float* pd = (float*)g_probD;
        const int base_b = b * (DD * UP);
        const int d0 = t + u;
        pd[2 * (base_b + d0 * UP + u)] = first - lse;               // .x blank
        if (u < ll) {
            int lab = load_int(labels, b * (UU - 1) + u, is64);
            lab = lab < 0 ? 0 : (lab > VV - 1 ? VV - 1 : lab);
            const float lab_logit = __ldcs(base + lab);
            pd[2 * (base_b + (d0 + 1) * UP + (u + 1)) + 1] = lab_logit - lse;  // .y
        }
        __threadfence();                       // publish probs before counting
        atomicAdd(&g_cnt[b][d0], 1);
    }
}

extern "C" void kernel_launch(void* const* d_in, const int* in_sizes, int n_in,
                              void* d_out, int out_size)
{
    const float* logits = (const float*)d_in[0];
    const void* labels = d_in[1];
    const void* label_lengths = d_in[2];
    const int* attention_mask = (const int*)d_in[3];
    float* out = (float*)d_out;

    const int grid = BB + (NCELLS + 7) / 8;
    fused_kernel<<<grid, 256>>>(logits, labels, label_lengths, attention_mask, out);
}

// round 14
// speedup vs baseline: 1.8139x; 1.8139x over previous
#include <cuda_runtime.h>
#include <cuda_bf16.h>
#include <math.h>

// Problem constants: B=4, MAX_T=200, MAX_U=101, VOCAB=1024
#define BB 4
#define TT 200
#define UU 101
#define UP 104                    // padded U stride (16B alignment for float4)
#define VV 1024
#define DD (TT + UU - 1)          // 300 anti-diagonals
#define DP (DD + 12)              // +12 pad diagonals: clamp-free prefetch
#define NCELLS (BB * TT * UU)     // 80800
#define SHIFT 7.5f                // per-step prob scaling: store exp(lp + SHIFT)

// Scratch. Diagonal-major, padded, interleaved SCALED PROBS:
//   g_probD[b][d*UP+u] = {exp(blank_lp+SHIFT), exp(label_lp+SHIFT)}
// Never-written slots stay 0.0f forever (zero-init, deterministic rewrites),
// which the prob-domain recursion relies on for boundary/dead cells.
__device__ __align__(16) float2 g_probD[BB * DP * UP];
__device__ float g_loss[BB];
__device__ int   g_valid[BB];
__device__ unsigned g_ticket;     // zero-init; last alpha block resets after use

// ---------------------------------------------------------------------------
// Per-warp helpers (all 32 lanes participate). int64 labels < 1024 => every
// odd int32 word is 0 (P[false positive] ~ 1024^-64).
// ---------------------------------------------------------------------------
__device__ __forceinline__ int warp_detect_is64(const int* __restrict__ labels_i32)
{
    const int lane = threadIdx.x & 31;
    int ok = 1;
#pragma unroll
    for (int i = 1 + 2 * lane; i < 256; i += 64)
        ok &= (labels_i32[i] == 0);
    return __all_sync(0xffffffffu, ok);
}

__device__ __forceinline__ int warp_input_len(const int* __restrict__ attention_mask, int b)
{
    const int lane = threadIdx.x & 31;
    int acc = 0;
#pragma unroll
    for (int k = lane; k < TT; k += 32)
        acc += attention_mask[b * TT + k];
#pragma unroll
    for (int off = 16; off > 0; off >>= 1)
        acc += __shfl_xor_sync(0xffffffffu, acc, off);
    return acc < 1 ? 1 : (acc > TT ? TT : acc);
}

__device__ __forceinline__ int load_int(const void* p, int idx, int is64)
{
    return is64 ? (int)((const long long*)p)[idx] : ((const int*)p)[idx];
}

// ---------------------------------------------------------------------------
// Kernel 1: streaming logsumexp over V=1024 per live cell; one warp/cell.
// Writes SCALED PROBS exp(lp + SHIFT) in diagonal-major padded layout at the
// CONSUMER position:
//   blank of (t,u)    -> g_probD[b][(t+u)*UP + u].x
//   label_lp of (t,u) -> g_probD[b][(t+u+1)*UP + (u+1)].y
// Dead cells (u > ll || t >= il) exit before any logits loads.
// ---------------------------------------------------------------------------
__global__ void __launch_bounds__(256)
lse_kernel(const float* __restrict__ logits,
           const void* __restrict__ labels,
           const void* __restrict__ label_lengths,
           const int* __restrict__ attention_mask)
{
    const int warp = threadIdx.x >> 5;
    const int lane = threadIdx.x & 31;
    const int cell = blockIdx.x * 8 + warp;
    if (cell >= NCELLS) return;

    const int b = cell / (TT * UU);
    const int rem = cell - b * (TT * UU);
    const int t = rem / UU;
    const int u = rem - t * UU;

    const int is64 = warp_detect_is64((const int*)labels);
    int ll = load_int(label_lengths, b, is64);
    ll = ll < 0 ? 0 : (ll > UU - 1 ? UU - 1 : ll);
    const int il = warp_input_len(attention_mask, b);
    if (u > ll || t >= il) return;          // dead cell: skip all logits loads

    const float* base = logits + (size_t)cell * VV;
    const float4* p = (const float4*)base;

    float s = 0.f;
    float first = 0.f;   // lane 0, i=0, .x == blank logit
#pragma unroll
    for (int i = 0; i < 8; i++) {
        float4 v = __ldcs(p + i * 32 + lane);      // streaming: keep probD in L2
        if (i == 0) first = v.x;
        s += __expf(v.x) + __expf(v.y) + __expf(v.z) + __expf(v.w);
    }
#pragma unroll
    for (int off = 16; off > 0; off >>= 1)
        s += __shfl_xor_sync(0xffffffffu, s, off);

    const float lse = __logf(s);

    if (lane == 0) {
        float* pd = (float*)g_probD;
        const int base_b = b * (DP * UP);
        pd[2 * (base_b + (t + u) * UP + u)] = __expf(first - lse + SHIFT);  // .x
        if (u < ll) {
            int lab = load_int(labels, b * (UU - 1) + u, is64);
            lab = lab < 0 ? 0 : (lab > VV - 1 ? VV - 1 : lab);
            const float lab_logit = __ldcs(base + lab);
            pd[2 * (base_b + (t + u + 1) * UP + (u + 1)) + 1] =
                __expf(lab_logit - lse + SHIFT);                            // .y
        }
    }
}

// ---------------------------------------------------------------------------
// Kernel 2: PROB-DOMAIN alpha wavefront. One warp per sample, 4 u per lane.
//   A(d,u) = A(d-1,u)*pb + A(d-1,u-1)*pl        (2 FMA-class ops per cell)
// Boundary/dead cells are exact zeros (never-written probD slots are 0), so
// no selects are needed in the loop. Seed: A(-1 virtual) has lane0.a0 = 1.
// Warp-max renormalization every 12 diagonals; running log-scale accumulator.
// Final: log alpha = log(A) + lscale - SHIFT*(target_d+1).
// ---------------------------------------------------------------------------
__global__ void __launch_bounds__(32)
alpha_kernel(const void* __restrict__ labels,
             const void* __restrict__ label_lengths,
             const int* __restrict__ attention_mask,
             float* __restrict__ out)
{
    const int b = blockIdx.x;
    const int lane = threadIdx.x;

    const int is64 = warp_detect_is64((const int*)labels);
    const int il = warp_input_len(attention_mask, b);
    int ll = load_int(label_lengths, b, is64);
    ll = ll < 0 ? 0 : (ll > UU - 1 ? UU - 1 : ll);
    const int target_d = (il - 1) + ll;

    const float2* pD = g_probD + b * (DP * UP);
    const int u0 = lane * 4;
    const int uL = (u0 <= 100) ? u0 : 100;   // EVEN -> float4-aligned, <= UP-4
    const float lmask = (lane == 0) ? 0.f : 1.f;

    // 12-deep prefetch with NAMED registers (padded array: no clamp needed).
    float4 pA0, pB0, pA1, pB1, pA2, pB2, pA3, pB3, pA4, pB4, pA5, pB5;
    float4 pA6, pB6, pA7, pB7, pA8, pB8, pA9, pB9, pA10, pB10, pA11, pB11;
#define PF_LOAD(PA, PB, K)                                                    \
    {                                                                         \
        const float4* p_ = (const float4*)(pD + (K) * UP + uL);               \
        PA = p_[0]; PB = p_[1];                                               \
    }
    PF_LOAD(pA0, pB0, 0)  PF_LOAD(pA1, pB1, 1)  PF_LOAD(pA2, pB2, 2)
    PF_LOAD(pA3, pB3, 3)  PF_LOAD(pA4, pB4, 4)  PF_LOAD(pA5, pB5, 5)
    PF_LOAD(pA6, pB6, 6)  PF_LOAD(pA7, pB7, 7)  PF_LOAD(pA8, pB8, 8)
    PF_LOAD(pA9, pB9, 9)  PF_LOAD(pA10, pB10, 10) PF_LOAD(pA11, pB11, 11)
#undef PF_LOAD

    float a0 = (lane == 0) ? 1.f : 0.f;      // virtual A(-1): seeds A(0,0)=pb00
    float a1 = 0.f, a2 = 0.f, a3 = 0.f;
    float lscale = 0.f;

#define ALPHA_STEP(PA, PB, DCUR)                                              \
    {                                                                         \
        const float4 cA = PA, cB = PB;                                        \
        const float4* pp = (const float4*)(pD + ((DCUR) + 12) * UP + uL);     \
        PA = pp[0]; PB = pp[1];                                               \
        const float left0 = __shfl_up_sync(0xffffffffu, a3, 1) * lmask;       \
        const float n0 = fmaf(a0, cA.x, left0 * cA.y);                        \
        const float n1 = fmaf(a1, cA.z, a0 * cA.w);                           \
        const float n2 = fmaf(a2, cB.x, a1 * cB.y);                           \
        const float n3 = fmaf(a3, cB.z, a2 * cB.w);                           \
        a0 = n0; a1 = n1; a2 = n2; a3 = n3;                                   \
    }

    int d = 0;
    for (; d + 11 <= target_d; d += 12) {
        ALPHA_STEP(pA0, pB0, d)
        ALPHA_STEP(pA1, pB1, d + 1)
        ALPHA_STEP(pA2, pB2, d + 2)
        ALPHA_STEP(pA3, pB3, d + 3)
        ALPHA_STEP(pA4, pB4, d + 4)
        ALPHA_STEP(pA5, pB5, d + 5)
        ALPHA_STEP(pA6, pB6, d + 6)
        ALPHA_STEP(pA7, pB7, d + 7)
        ALPHA_STEP(pA8, pB8, d + 8)
        ALPHA_STEP(pA9, pB9, d + 9)
        ALPHA_STEP(pA10, pB10, d + 10)
        ALPHA_STEP(pA11, pB11, d + 11)
        // Renormalize by warp max; accumulate log scale (warp-uniform).
        float mx = fmaxf(fmaxf(a0, a1), fmaxf(a2, a3));
#pragma unroll
        for (int off = 16; off > 0; off >>= 1)
            mx = fmaxf(mx, __shfl_xor_sync(0xffffffffu, mx, off));
        const float inv = __frcp_rn(mx);
        a0 *= inv; a1 *= inv; a2 *= inv; a3 *= inv;
        lscale += __logf(mx);
    }
    // tail: warp-uniform guards; padded array keeps prefetch in-bounds
    if (d     <= target_d) ALPHA_STEP(pA0, pB0, d)
    if (d + 1 <= target_d) ALPHA_STEP(pA1, pB1, d + 1)
    if (d + 2 <= target_d) ALPHA_STEP(pA2, pB2, d + 2)
    if (d + 3 <= target_d) ALPHA_STEP(pA3, pB3, d + 3)
    if (d + 4 <= target_d) ALPHA_STEP(pA4, pB4, d + 4)
    if (d + 5 <= target_d) ALPHA_STEP(pA5, pB5, d + 5)
    if (d + 6 <= target_d) ALPHA_STEP(pA6, pB6, d + 6)
    if (d + 7 <= target_d) ALPHA_STEP(pA7, pB7, d + 7)
    if (d + 8 <= target_d) ALPHA_STEP(pA8, pB8, d + 8)
    if (d + 9 <= target_d) ALPHA_STEP(pA9, pB9, d + 9)
    if (d + 10 <= target_d) ALPHA_STEP(pA10, pB10, d + 10)
#undef ALPHA_STEP

    // Result: A(target_d, ll) lives in lane ll>>2, slot ll&3.
    const int src_lane = ll >> 2;
    const int sub = ll & 3;
    const float r0 = __shfl_sync(0xffffffffu, a0, src_lane);
    const float r1 = __shfl_sync(0xffffffffu, a1, src_lane);
    const float r2 = __shfl_sync(0xffffffffu, a2, src_lane);
    const float r3 = __shfl_sync(0xffffffffu, a3, src_lane);
    const float r = (sub == 0) ? r0 : (sub == 1) ? r1 : (sub == 2) ? r2 : r3;

    if (lane == 0) {
        const float log_alpha = __logf(r) + lscale - SHIFT * (float)(target_d + 1);
        const bool valid = (il > 0) && (ll > 0);
        g_loss[b] = valid ? -log_alpha : 0.f;
        g_valid[b] = valid ? 1 : 0;

        // Fused mean reduction: last warp to arrive writes the scalar.
        __threadfence();
        const unsigned tk = atomicAdd(&g_ticket, 1u);
        if (tk == BB - 1) {
            __threadfence();
            float s = 0.f;
            int nv = 0;
#pragma unroll
            for (int i = 0; i < BB; i++) { s += g_loss[i]; nv += g_valid[i]; }
            out[0] = s / (float)(nv > 0 ? nv : 1);
            g_ticket = 0;                  // reset for next graph replay
            __threadfence();
        }
    }
}

extern "C" void kernel_launch(void* const* d_in, const int* in_sizes, int n_in,
                              void* d_out, int out_size)
{
    const float* logits = (const float*)d_in[0];
    const void* labels = d_in[1];
    const void* label_lengths = d_in[2];
    const int* attention_mask = (const int*)d_in[3];
    float* out = (float*)d_out;

    lse_kernel<<<(NCELLS + 7) / 8, 256>>>(logits, labels, label_lengths, attention_mask);
    alpha_kernel<<<BB, 32>>>(labels, label_lengths, attention_mask, out);
}